// round 15
// baseline (speedup 1.0000x reference)
#include <cuda_runtime.h>
#include <cuda_fp16.h>
#include <math.h>
#include <stdint.h>

#define BB 64
#define NN 512
#define RR 1024
#define KTOP 256
#define BR (BB*RR)
#define NGE ((long)BB*NN*RR)

// ---------------- device scratch ----------------
__device__ float g_adj[(long)BB*NN*NN];
__device__ unsigned g_minu[BB];
__device__ float g_xcat[BB*3072];
__device__ float g_gates[BB*4096];
__device__ float g_gates2[BB*4096];
__device__ float g_part[4*BB*4096];
__device__ float g_ht1[BB*RR];
__device__ float g_ht2[BB*RR];
__device__ float g_pvec[BB*RR];
__device__ float g_srow[BB*NN];
__device__ float g_dvec[BB*NN];
__device__ unsigned g_attu[BB*RR];
__device__ float g_xl[BB*2048];
__device__ float g_hatt[BR];
__device__ float g_catt[BR];
__device__ float g_hlang[BR];
__device__ float g_clang[BR];
// rank-1 machinery
__device__ float g_Vra[BB*RR], g_Vca[BB*RR];
__device__ float g_Vrb[RR], g_Vcb[RR];
__device__ float g_smm[BB], g_sm1[BB], g_s1m[BB], g_s11[1];
__device__ float g_ra[BB*NN], g_rb[BB*NN], g_ca[BB*NN], g_cb[BB*NN];

__device__ __half g_Ph[NGE];              // GEM(hi) -> Z1^T
__device__ __half g_Qh[NGE], g_Ql[NGE];   // U -> X2
__device__ __half g_Sh[NGE], g_Sl[NGE];   // X1 -> Z2^T
__device__ __half g_Z0h[NGE];
__device__ __half g_ADJh[(long)BB*NN*NN];
__device__ __half g_W1h[1048576], g_W1l[1048576];
__device__ __half g_W2h[1048576], g_W2l[1048576];
__device__ __half g_Wmh[1048576], g_Wml[1048576];
__device__ __half g_G0h[1048576];
__device__ __half g_G1h[1048576];
__device__ __half g_G2h[1048576];

__device__ __forceinline__ unsigned fenc(float f){
    unsigned u = __float_as_uint(f);
    return (u & 0x80000000u) ? ~u : (u | 0x80000000u);
}
__device__ __forceinline__ float fdec(unsigned v){
    unsigned u = (v & 0x80000000u) ? (v ^ 0x80000000u) : ~v;
    return __uint_as_float(u);
}

// ---------------- warp MMA helpers ----------------
__device__ __forceinline__ uint32_t smem_u32(const void* p){
    uint32_t a;
    asm("{ .reg .u64 t; cvta.to.shared.u64 t, %1; cvt.u32.u64 %0, t; }" : "=r"(a) : "l"(p));
    return a;
}
__device__ __forceinline__ uint32_t swz64(uint32_t x){ return x ^ ((x>>3)&0x30u); }
__device__ __forceinline__ void ldm4(uint32_t* r, uint32_t addr){
    asm volatile("ldmatrix.sync.aligned.m8n8.x4.shared.b16 {%0,%1,%2,%3}, [%4];"
        : "=r"(r[0]),"=r"(r[1]),"=r"(r[2]),"=r"(r[3]) : "r"(addr));
}
__device__ __forceinline__ void mma16816(float* d, const uint32_t* a, const uint32_t* b){
    asm volatile("mma.sync.aligned.m16n8k16.row.col.f32.f16.f16.f32 "
        "{%0,%1,%2,%3}, {%4,%5,%6,%7}, {%8,%9}, {%0,%1,%2,%3};"
        : "+f"(d[0]),"+f"(d[1]),"+f"(d[2]),"+f"(d[3])
        : "r"(a[0]),"r"(a[1]),"r"(a[2]),"r"(a[3]), "r"(b[0]),"r"(b[1]));
}
__device__ __forceinline__ void cpasync16(uint32_t dst, const void* src){
    asm volatile("cp.async.cg.shared.global [%0], [%1], 16;" :: "r"(dst), "l"(src));
}

// ---------------- fp16 hi/lo tensor-core GEMM ----------------
// PASSES: 1 = Ah@Bh; 2 = Ah@(Bh+Bl); 3 = AhBh+AhBl+AlBh; 4 = (Ah+Al)@Bh.
// outMode: 0 = plain fp32; 1 = fp16 hi(/lo) row-major; 2 = fp16 transposed; 3 = atomicMax attu.
#define MMA_SMEM (3*32768+1024)

template<int PASSES>
__global__ void __launch_bounds__(128,2) hmma_gemm(
    const __half* __restrict__ Ah, const __half* __restrict__ Al, int lda, long sA,
    const __half* __restrict__ Bh, const __half* __restrict__ Bl, int ldb, long sB,
    int K, int rowsPerZ, int outMode, int relu,
    float* Cf, int ldc,
    __half* Ch, __half* Cl, int ldch,
    const float* __restrict__ bias, const float* __restrict__ addv,
    const float* __restrict__ rs, const float* __restrict__ ps,
    unsigned* __restrict__ attu)
{
    constexpr bool A_LO = (PASSES==3 || PASSES==4);
    constexpr bool B_LO = (PASSES==2 || PASSES==3);
    extern __shared__ char smraw[];
    uint32_t sb0 = smem_u32(smraw);
    uint32_t sb  = (sb0 + 1023u) & ~1023u;
    const int tid = threadIdx.x, wid = tid>>5, lane = tid&31;

    const __half* A0 = Ah + blockIdx.z*sA;
    const __half* A1 = A_LO ? (Al + blockIdx.z*sA) : nullptr;
    const __half* B0 = Bh + blockIdx.z*sB;
    const __half* B1 = B_LO ? (Bl + blockIdx.z*sB) : nullptr;
    const int rowBase = blockIdx.y*128, colBase = blockIdx.x*128;
    const int NC = K >> 5;

    const int wr = wid>>1, wc = wid&1;
    const int lr = lane&7, q = lane>>3;
    const int aRowOff = ((q&1)<<3) + lr;
    const int aKbOff  = (q>>1)<<4;
    const int bRowOff = ((q>>1)<<3) + lr;
    const int bKbOff  = (q&1)<<4;

    const int cp_row = tid>>2;
    const int cp_u   = tid&3;

    float acc[4][8][4];
    #pragma unroll
    for (int a=0;a<4;a++)
        #pragma unroll
        for (int b=0;b<8;b++)
            #pragma unroll
            for (int c=0;c<4;c++) acc[a][b][c]=0.f;

    auto load_chunk = [&](int ci, int s){
        const int k0 = ci<<5;
        const uint32_t st = sb + s*32768;
        #pragma unroll
        for (int j=0;j<4;j++){
            int r = cp_row + j*32;
            uint32_t doff = swz64((uint32_t)(r*64 + cp_u*16));
            long aoff = (long)(rowBase+r)*lda + k0 + cp_u*8;
            long boff = (long)(colBase+r)*ldb + k0 + cp_u*8;
            cpasync16(st +         doff, A0 + aoff);
            if (A_LO) cpasync16(st + 8192 + doff, A1 + aoff);
            cpasync16(st + 16384 + doff, B0 + boff);
            if (B_LO) cpasync16(st + 24576 + doff, B1 + boff);
        }
        asm volatile("cp.async.commit_group;" ::: "memory");
    };

    load_chunk(0, 0);
    if (NC > 1) load_chunk(1, 1);

    int sidx = 0;
    int nidx = (NC > 2) ? 2 : 0;
    for (int i=0;i<NC;i++){
        if (i+1 < NC) asm volatile("cp.async.wait_group 1;" ::: "memory");
        else          asm volatile("cp.async.wait_group 0;" ::: "memory");
        __syncthreads();
        if (i+2 < NC){
            load_chunk(i+2, nidx);
            nidx = (nidx==2)?0:nidx+1;
        }
        const uint32_t st = sb + sidx*32768;
        sidx = (sidx==2)?0:sidx+1;
        #pragma unroll
        for (int ks=0;ks<2;ks++){
            const uint32_t kb = ks<<5;
            uint32_t bh[4][4], bl[4][4], af[4][4];
            #pragma unroll
            for (int t=0;t<4;t++){
                uint32_t ro = (uint32_t)((wc*64 + t*16 + bRowOff)*64) + kb + bKbOff;
                ldm4(bh[t], st + 16384 + swz64(ro));
                if (B_LO) ldm4(bl[t], st + 24576 + swz64(ro));
            }
            #pragma unroll
            for (int mi=0;mi<4;mi++){
                uint32_t ro = (uint32_t)((wr*64 + mi*16 + aRowOff)*64) + kb + aKbOff;
                ldm4(af[mi], st + swz64(ro));
            }
            #pragma unroll
            for (int mi=0;mi<4;mi++)
                #pragma unroll
                for (int t=0;t<4;t++){
                    mma16816(acc[mi][2*t],   af[mi], &bh[t][0]);
                    mma16816(acc[mi][2*t+1], af[mi], &bh[t][2]);
                }
            if (B_LO){
                #pragma unroll
                for (int mi=0;mi<4;mi++)
                    #pragma unroll
                    for (int t=0;t<4;t++){
                        mma16816(acc[mi][2*t],   af[mi], &bl[t][0]);
                        mma16816(acc[mi][2*t+1], af[mi], &bl[t][2]);
                    }
            }
            if (A_LO){
                #pragma unroll
                for (int mi=0;mi<4;mi++){
                    uint32_t ro = (uint32_t)((wr*64 + mi*16 + aRowOff)*64) + kb + aKbOff;
                    ldm4(af[mi], st + 8192 + swz64(ro));
                }
                #pragma unroll
                for (int mi=0;mi<4;mi++)
                    #pragma unroll
                    for (int t=0;t<4;t++){
                        mma16816(acc[mi][2*t],   af[mi], &bh[t][0]);
                        mma16816(acc[mi][2*t+1], af[mi], &bh[t][2]);
                    }
            }
        }
    }

    // ---- epilogue ----
    const int cpair = (lane&3)*2;
    if (outMode == 0){
        #pragma unroll
        for (int mi=0;mi<4;mi++){
            #pragma unroll
            for (int rr=0;rr<2;rr++){
                const int gr = blockIdx.z*rowsPerZ + rowBase + wr*64 + mi*16 + (lane>>2) + rr*8;
                #pragma unroll
                for (int ni=0;ni<8;ni++){
                    const int c = colBase + wc*64 + ni*8 + cpair;
                    *(float2*)(Cf + (long)gr*ldc + c) =
                        make_float2(acc[mi][ni][rr*2+0], acc[mi][ni][rr*2+1]);
                }
            }
        }
    } else if (outMode == 3){
        const int b = blockIdx.z;
        #pragma unroll
        for (int ni=0;ni<8;ni++){
            float mx0 = 0.f, mx1 = 0.f;
            const int c = colBase + wc*64 + ni*8 + cpair;
            #pragma unroll
            for (int mi=0;mi<4;mi++){
                #pragma unroll
                for (int rr=0;rr<2;rr++){
                    const int gr = blockIdx.z*rowsPerZ + rowBase + wr*64 + mi*16 + (lane>>2) + rr*8;
                    const float psv = ps ? ps[gr] : 1.f;
                    float x0 = acc[mi][ni][rr*2+0] + bias[c];
                    float x1 = acc[mi][ni][rr*2+1] + bias[c+1];
                    x0 = fmaxf(x0,0.f)*psv; x1 = fmaxf(x1,0.f)*psv;
                    mx0 = fmaxf(mx0,x0); mx1 = fmaxf(mx1,x1);
                }
            }
            atomicMax(&attu[(long)b*RR + c],   __float_as_uint(mx0));
            atomicMax(&attu[(long)b*RR + c+1], __float_as_uint(mx1));
        }
    } else {
        #pragma unroll
        for (int mi=0;mi<4;mi++){
            #pragma unroll
            for (int rr=0;rr<2;rr++){
                const int r  = rowBase + wr*64 + mi*16 + (lane>>2) + rr*8;
                const int gr = blockIdx.z*rowsPerZ + r;
                const float rsv = rs ? rs[gr] : 1.f;
                const float psv = ps ? ps[gr] : 1.f;
                const float* avp = addv ? addv + (long)(gr>>9)*RR : nullptr;
                #pragma unroll
                for (int ni=0;ni<8;ni++){
                    const int c = colBase + wc*64 + ni*8 + cpair;
                    float x0 = acc[mi][ni][rr*2+0];
                    float x1 = acc[mi][ni][rr*2+1];
                    if (avp){ x0 += rsv*avp[c]; x1 += rsv*avp[c+1]; }
                    if (bias){ x0 += bias[c]; x1 += bias[c+1]; }
                    if (relu){ x0 = fmaxf(x0,0.f); x1 = fmaxf(x1,0.f); }
                    x0 *= psv; x1 *= psv;
                    __half h0 = __float2half_rn(x0);
                    __half h1 = __float2half_rn(x1);
                    if (outMode==1){
                        long o = (long)gr*ldch + c;
                        *(__half2*)(Ch+o) = __halves2half2(h0,h1);
                        if (Cl){
                            __half l0 = __float2half_rn(x0-__half2float(h0));
                            __half l1 = __float2half_rn(x1-__half2float(h1));
                            *(__half2*)(Cl+o) = __halves2half2(l0,l1);
                        }
                    } else {
                        long base = (long)(gr>>9)*((long)RR*NN) + (gr&511);
                        long o0 = base + (long)c*NN;
                        Ch[o0]=h0; Ch[o0+NN]=h1;
                        if (Cl){
                            Cl[o0]   = __float2half_rn(x0-__half2float(h0));
                            Cl[o0+NN]= __float2half_rn(x1-__half2float(h1));
                        }
                    }
                }
            }
        }
    }
}

// ---------------- FFMA split-K GEMM (small matmuls) ----------------
template<bool BT>
__global__ void __launch_bounds__(256) gemm_part(
    const float* __restrict__ A,int lda,
    const float* __restrict__ B,int ldb,
    float* __restrict__ C,int ldc,long partStride,int chunkK)
{
    __shared__ float As[16][64];
    __shared__ float Bs[16][64];
    const int tid = threadIdx.x;
    const int rowBase = blockIdx.y*64, colBase = blockIdx.x*64;
    const int kbeg = blockIdx.z*chunkK, kend = kbeg + chunkK;
    const int tx = tid & 15, ty = tid >> 4;
    float acc[4][4];
#pragma unroll
    for (int i=0;i<4;i++)
#pragma unroll
        for (int j=0;j<4;j++) acc[i][j]=0.f;

    for (int k0=kbeg;k0<kend;k0+=16){
#pragma unroll
        for (int i=tid*4;i<64*16;i+=256*4){
            int r=i>>4, kk=i&15;
            float4 v = *(const float4*)(A + (long)(rowBase+r)*lda + k0 + kk);
            As[kk+0][r]=v.x; As[kk+1][r]=v.y; As[kk+2][r]=v.z; As[kk+3][r]=v.w;
        }
        if (BT){
#pragma unroll
            for (int i=tid*4;i<64*16;i+=256*4){
                int r=i>>4, kk=i&15;
                float4 v = *(const float4*)(B + (long)(colBase+r)*ldb + k0 + kk);
                Bs[kk+0][r]=v.x; Bs[kk+1][r]=v.y; Bs[kk+2][r]=v.z; Bs[kk+3][r]=v.w;
            }
        } else {
#pragma unroll
            for (int i=tid*4;i<16*64;i+=256*4){
                int r=i>>6, cc=i&63;
                *(float4*)&Bs[r][cc] = *(const float4*)(B + (long)(k0+r)*ldb + colBase + cc);
            }
        }
        __syncthreads();
#pragma unroll
        for (int k=0;k<16;k++){
            float a[4], b[4];
            *(float4*)a = *(const float4*)&As[k][ty*4];
            *(float4*)b = *(const float4*)&Bs[k][tx*4];
#pragma unroll
            for (int i=0;i<4;i++)
#pragma unroll
                for (int j=0;j<4;j++) acc[i][j] = fmaf(a[i], b[j], acc[i][j]);
        }
        __syncthreads();
    }
    float* Cp = C + (long)blockIdx.z*partStride;
#pragma unroll
    for (int i=0;i<4;i++){
        int r = rowBase + ty*4 + i;
#pragma unroll
        for (int j=0;j<4;j++)
            Cp[(long)r*ldc + colBase + tx*4 + j] = acc[i][j];
    }
}
static void sgemm(bool BT,const float* A,int lda,const float* B,int ldb,float* Cpart,int ldc,
                  int M,int N,int K,int splits,cudaStream_t st=0){
    dim3 g(N/64, M/64, splits);
    int chunkK = K/splits;
    if (BT) gemm_part<true ><<<g,256,0,st>>>(A,lda,B,ldb,Cpart,ldc,(long)M*ldc,chunkK);
    else    gemm_part<false><<<g,256,0,st>>>(A,lda,B,ldb,Cpart,ldc,(long)M*ldc,chunkK);
}
__global__ void reduce_kernel(float* dst,const float* src,long len,int splits,int colmask,
                              const float* b1,const float* b2){
    long i = (long)blockIdx.x*blockDim.x+threadIdx.x;
    if (i >= len) return;
    float s = 0.f;
    for (int z=0;z<splits;z++) s += src[z*len+i];
    int col = (int)(i & colmask);
    if (b1) s += b1[col];
    if (b2) s += b2[col];
    dst[i] = s;
}

// ---------------- conversions ----------------
__device__ __forceinline__ void split1(float v, __half& h, __half& l){
    h = __float2half_rn(v);
    l = __float2half_rn(v - __half2float(h));
}
__global__ void conv_mask_kernel(const float* __restrict__ src, const float* __restrict__ mask,
                                 __half* __restrict__ dh, long n4, unsigned* minu){
    long i = (long)blockIdx.x*blockDim.x + threadIdx.x;
    if (i < BB && minu) minu[i] = 0xFFFFFFFFu;
    if (i >= n4) return;
    float4 v = ((const float4*)src)[i];
    float m = mask[i >> 8];
    __align__(8) __half h[4];
    h[0]=__float2half_rn(v.x*m); h[1]=__float2half_rn(v.y*m);
    h[2]=__float2half_rn(v.z*m); h[3]=__float2half_rn(v.w*m);
    ((uint2*)dh)[i] = *(uint2*)h;
}
__global__ void tconv2_kernel(const float* __restrict__ src, int ld,
                              __half* __restrict__ dh, __half* __restrict__ dl){
    __shared__ float t[32][33];
    int r0 = blockIdx.y*32, c0 = blockIdx.x*32;
    int tx = threadIdx.x, ty = threadIdx.y;
    for (int i=ty;i<32;i+=8)
        t[i][tx] = src[(long)(r0+i)*ld + c0+tx];
    __syncthreads();
    for (int i=ty;i<32;i+=8){
        __half h,l; split1(t[tx][i], h, l);
        long o = (long)(c0+i)*1024 + r0+tx;
        dh[o]=h; dl[o]=l;
    }
}
__global__ void tconv_kernel(const float* __restrict__ src, int rows, int cols,
                             __half* __restrict__ dh){
    __shared__ float t[32][33];
    int r0 = blockIdx.y*32, c0 = blockIdx.x*32;
    int tx = threadIdx.x, ty = threadIdx.y;
    for (int i=ty;i<32;i+=8)
        t[i][tx] = src[(long)(r0+i)*cols + c0+tx];
    __syncthreads();
    for (int i=ty;i<32;i+=8){
        long o = (long)(c0+i)*rows + r0+tx;
        dh[o] = __float2half_rn(t[tx][i]);
    }
}
__global__ void mv_kernel(const float* __restrict__ b, const float* __restrict__ W, int ld,
                          float* __restrict__ out){
    int f = blockIdx.x*blockDim.x + threadIdx.x;
    if (f >= RR) return;
    float s = 0.f;
    for (int o=0;o<RR;o++) s += b[o]*W[(long)o*ld + f];
    out[f] = s;
}
__global__ void scalars_kernel(const float* ht1,const float* ht2,const float* b1,const float* b2,
                               float* smm,float* sm1,float* s1m,float* s11){
    __shared__ float red[3][256];
    int b = blockIdx.x, t = threadIdx.x;
    const float* g1 = ht1 + b*RR;
    const float* g2 = ht2 + b*RR;
    float a0=0,a1=0,a2=0;
    for (int k=t;k<RR;k+=256){
        float x1=g1[k], x2=g2[k];
        a0 += x1*x2; a1 += x1*b2[k]; a2 += b1[k]*x2;
    }
    red[0][t]=a0; red[1][t]=a1; red[2][t]=a2; __syncthreads();
    for (int s=128;s>0;s>>=1){
        if (t<s){ red[0][t]+=red[0][t+s]; red[1][t]+=red[1][t+s]; red[2][t]+=red[2][t+s]; }
        __syncthreads();
    }
    if (t==0){ smm[b]=red[0][0]; sm1[b]=red[1][0]; s1m[b]=red[2][0]; }
    if (b==0){
        __shared__ float r2[256];
        float a=0;
        for (int k=t;k<RR;k+=256) a += b1[k]*b2[k];
        r2[t]=a; __syncthreads();
        for (int s=128;s>0;s>>=1){ if (t<s) r2[t]+=r2[t+s]; __syncthreads(); }
        if (t==0) s11[0]=r2[0];
    }
}
__global__ void ranks_kernel(const __half* __restrict__ G,
                             const float* __restrict__ Vra,const float* __restrict__ Vrb,
                             const float* __restrict__ Vca,const float* __restrict__ Vcb,
                             const float* smm,const float* sm1,const float* s1m,const float* s11,
                             const float* __restrict__ mask,
                             float* ra,float* rb,float* ca,float* cb){
    int row = blockIdx.x*8 + (threadIdx.x>>5);
    int lane = threadIdx.x & 31;
    int b = row >> 9;
    const __half2* g2p = (const __half2*)(G + (long)row*RR);
    const float* vra = Vra + b*RR;
    const float* vca = Vca + b*RR;
    float d1=0,d2=0,d3=0,d4=0;
    for (int k=lane;k<RR/2;k+=32){
        __half2 h = g2p[k];
        float g0 = __low2float(h), g1 = __high2float(h);
        int f = k*2;
        d1 += g0*vra[f] + g1*vra[f+1];
        d2 += g0*Vrb[f] + g1*Vrb[f+1];
        d3 += g0*vca[f] + g1*vca[f+1];
        d4 += g0*Vcb[f] + g1*Vcb[f+1];
    }
    #pragma unroll
    for (int o=16;o;o>>=1){
        d1 += __shfl_xor_sync(0xffffffffu,d1,o);
        d2 += __shfl_xor_sync(0xffffffffu,d2,o);
        d3 += __shfl_xor_sync(0xffffffffu,d3,o);
        d4 += __shfl_xor_sync(0xffffffffu,d4,o);
    }
    if (lane==0){
        ra[row] = d1 + s1m[b];
        rb[row] = d2 + s11[0];
        ca[row] = d3 + smm[b]*mask[row] + sm1[b];
        cb[row] = d4;
    }
}
__global__ void clear_attu(unsigned* attu){
    int i = blockIdx.x*blockDim.x + threadIdx.x;
    if (i < BB*RR) attu[i] = 0u;
}
// adj += rank-1 terms, compute per-batch min
__global__ void adj_epi_kernel(float* __restrict__ adj,
                               const float* __restrict__ ra,const float* __restrict__ rb,
                               const float* __restrict__ ca,const float* __restrict__ cb,
                               const float* __restrict__ mask, unsigned* minu){
    int row = blockIdx.x*8 + (threadIdx.x>>5);
    int lane = threadIdx.x & 31;
    int zb = (row>>9)<<9;
    float* a = adj + (long)row*NN;
    const float rav = ra[row], rbv = rb[row], mrow = mask[row];
    const float* mkc = mask + zb;
    const float* cac = ca + zb;
    const float* cbc = cb + zb;
    float lmin = INFINITY;
    for (int k=lane*4; k<NN; k+=128){
        float4 v  = *(float4*)(a+k);
        float4 m4 = *(const float4*)(mkc+k);
        float4 c4 = *(const float4*)(cac+k);
        float4 b4 = *(const float4*)(cbc+k);
        v.x += rav*m4.x + mrow*c4.x + rbv + b4.x;
        v.y += rav*m4.y + mrow*c4.y + rbv + b4.y;
        v.z += rav*m4.z + mrow*c4.z + rbv + b4.z;
        v.w += rav*m4.w + mrow*c4.w + rbv + b4.w;
        *(float4*)(a+k) = v;
        lmin = fminf(lmin, fminf(fminf(v.x,v.y), fminf(v.z,v.w)));
    }
    #pragma unroll
    for (int o=16;o;o>>=1) lmin = fminf(lmin, __shfl_xor_sync(0xffffffffu, lmin, o));
    if (lane==0) atomicMin(&minu[row>>9], fenc(lmin));
}

// ---------------- pointwise / reductions ----------------
__device__ __forceinline__ float sigm(float x){ return 1.f/(1.f+__expf(-x)); }

__global__ void concat3_kernel(const float* a,const float* b,const float* c,float* out){
    int idx = blockIdx.x*blockDim.x+threadIdx.x;
    if (idx >= BB*3072) return;
    int bb = idx/3072, j = idx%3072;
    out[idx] = (j<1024) ? a[bb*1024+j] : (j<2048 ? b[bb*1024+j-1024] : c[bb*1024+j-2048]);
}
__global__ void concat2_kernel(const unsigned* a,const float* b,float* out){
    int idx = blockIdx.x*blockDim.x+threadIdx.x;
    if (idx >= BB*2048) return;
    int bb = idx/2048, j = idx%2048;
    out[idx] = (j<1024) ? __uint_as_float(a[bb*1024+j]) : b[bb*1024+j-1024];
}
__global__ void lstm_kernel(const float* gates,const float* c_prev,float* h_out,float* c_out){
    int idx = blockIdx.x*blockDim.x+threadIdx.x;
    if (idx >= BR) return;
    int bb = idx >> 10, r = idx & 1023;
    const float* g = gates + bb*4096;
    float c = sigm(g[1024+r])*c_prev[idx] + sigm(g[r])*tanhf(g[2048+r]);
    h_out[idx] = sigm(g[3072+r])*tanhf(c);
    c_out[idx] = c;
}
__global__ void __launch_bounds__(512) topk_kernel(const float* __restrict__ Adj,
                                                   const unsigned* __restrict__ minu,
                                                   const float* __restrict__ mask,
                                                   __half* __restrict__ Araw, float* dvec){
    __shared__ unsigned long long sk[NN];
    __shared__ float red[NN];
    int row = blockIdx.x, t = threadIdx.x, bb = row >> 9;
    float mrow = mask[row];
    float mn = fdec(minu[bb]);
    float v = (Adj[(long)row*NN + t] - mn) * mrow;
    unsigned long long key = ((unsigned long long)__float_as_uint(v) << 32) | (unsigned)(NN-1-t);
    #pragma unroll
    for (unsigned k2=2;k2<=NN;k2<<=1){
        for (unsigned j=k2>>1;j>0;j>>=1){
            unsigned long long other;
            if (j < 32){
                unsigned lo = __shfl_xor_sync(0xffffffffu, (unsigned)key, j);
                unsigned hi = __shfl_xor_sync(0xffffffffu, (unsigned)(key>>32), j);
                other = ((unsigned long long)hi << 32) | lo;
            } else {
                sk[t] = key; __syncthreads();
                other = sk[t ^ j]; __syncthreads();
            }
            bool lower = ((t & j) == 0);
            bool desc  = ((t & k2) == 0);
            unsigned long long mx  = (key > other) ? key : other;
            unsigned long long mnk = (key > other) ? other : key;
            key = (desc == lower) ? mx : mnk;
        }
    }
    int col = (NN-1) - (int)(unsigned)(key & 0xffffffffu);
    float val = __uint_as_float((unsigned)(key >> 32));
    __half* ar = Araw + (long)row*NN;
    ar[t] = __float2half_rn(0.f);
    __syncthreads();
    float s = 0.f;
    if (t < KTOP){
        ar[col] = __float2half_rn(val);
        s = val;
    }
    red[t]=s; __syncthreads();
    for (int st=NN/2;st>0;st>>=1){ if (t<st) red[t]+=red[t+st]; __syncthreads(); }
    if (t==0) dvec[row] = (red[0] > 0.f) ? rsqrtf(red[0]) : 0.f;
}
__global__ void rowfinal_kernel(__half* __restrict__ Ah, const float* __restrict__ dvec,
                                const float* __restrict__ mask, float* __restrict__ srow){
    int row = blockIdx.x*8 + (threadIdx.x>>5);
    int lane = threadIdx.x & 31;
    int bb = row >> 9;
    const float dr = dvec[row];
    const float* dc = dvec + (bb<<9);
    const float* m  = mask + (bb<<9);
    __half* ar = Ah + (long)row*NN;
    float s = 0.f;
    for (int k=lane*4; k<NN; k+=128){
        uint2 raw = *(uint2*)(ar+k);
        __align__(8) __half h[4]; *(uint2*)h = raw;
        float4 d4 = *(const float4*)(dc+k);
        float4 m4 = *(const float4*)(m+k);
        float x0=__half2float(h[0])*dr*d4.x, x1=__half2float(h[1])*dr*d4.y;
        float x2=__half2float(h[2])*dr*d4.z, x3=__half2float(h[3])*dr*d4.w;
        s += x0*m4.x + x1*m4.y + x2*m4.z + x3*m4.w;
        h[0]=__float2half_rn(x0); h[1]=__float2half_rn(x1);
        h[2]=__float2half_rn(x2); h[3]=__float2half_rn(x3);
        *(uint2*)(ar+k) = *(uint2*)h;
    }
    for (int o=16;o;o>>=1) s += __shfl_xor_sync(0xffffffffu, s, o);
    if (lane==0) srow[row] = s;
}
__global__ void pack_kernel(const float* hatt,const float* catt,
                            const float* hlang,const float* clang,float* out,int out_size){
    int i = blockIdx.x*blockDim.x+threadIdx.x;
    if (i >= BR) return;
    out[i] = hlang[i];
    if (out_size >= 5*BR){
        out[1*BR+i] = hatt[i];
        out[2*BR+i] = hlang[i];
        out[3*BR+i] = catt[i];
        out[4*BR+i] = clang[i];
    }
}

// ---------------- host driver ----------------
struct Ptrs {
    float *adj,*xcat,*gates,*gates2,*part,*ht1,*ht2,*pvec,*srow,*dvec,*xl,*hatt,*catt,*hlang,*clang;
    float *Vra,*Vca,*Vrb,*Vcb,*smm,*sm1,*s1m,*s11,*ra,*rb,*ca,*cb;
    unsigned *minu,*attu;
    __half *Ph,*Qh,*Ql,*Sh,*Sl,*Z0h,*ADJh;
    __half *W1h,*W1l,*W2h,*W2l,*Wmh,*Wml,*G0h,*G1h,*G2h;
};
static Ptrs P;
static bool g_init = false;
static cudaStream_t g_s2;
static cudaEvent_t g_ev1, g_ev_mv, g_ev_adj, g_ev3;

extern "C" void kernel_launch(void* const* d_in, const int* in_sizes, int n_in,
                              void* d_out, int out_size)
{
    const float* xt   = (const float*)d_in[0];
    const float* fc   = (const float*)d_in[1];
    const float* ge   = (const float*)d_in[2];
    const float* sh   = (const float*)d_in[4];
    const float* sc   = (const float*)d_in[5];
    const float* mask = (const float*)d_in[6];
    const float* aWih = (const float*)d_in[7];
    const float* aWhh = (const float*)d_in[8];
    const float* abih = (const float*)d_in[9];
    const float* abhh = (const float*)d_in[10];
    const float* lWih = (const float*)d_in[11];
    const float* lWhh = (const float*)d_in[12];
    const float* lbih = (const float*)d_in[13];
    const float* lbhh = (const float*)d_in[14];
    const float* e1W  = (const float*)d_in[15];
    const float* e1b  = (const float*)d_in[16];
    const float* e2W  = (const float*)d_in[17];
    const float* e2b  = (const float*)d_in[18];
    const float* gW0  = (const float*)d_in[19];
    const float* gb0  = (const float*)d_in[20];
    const float* gW1  = (const float*)d_in[21];
    const float* gb1  = (const float*)d_in[22];
    const float* gW2  = (const float*)d_in[23];
    const float* gb2  = (const float*)d_in[24];
    (void)in_sizes; (void)n_in;
    float* out = (float*)d_out;

    if (!g_init){
        cudaGetSymbolAddress((void**)&P.adj,  g_adj);
        cudaGetSymbolAddress((void**)&P.minu, g_minu);
        cudaGetSymbolAddress((void**)&P.xcat, g_xcat);
        cudaGetSymbolAddress((void**)&P.gates,g_gates);
        cudaGetSymbolAddress((void**)&P.gates2,g_gates2);
        cudaGetSymbolAddress((void**)&P.part, g_part);
        cudaGetSymbolAddress((void**)&P.ht1,  g_ht1);
        cudaGetSymbolAddress((void**)&P.ht2,  g_ht2);
        cudaGetSymbolAddress((void**)&P.pvec, g_pvec);
        cudaGetSymbolAddress((void**)&P.srow, g_srow);
        cudaGetSymbolAddress((void**)&P.dvec, g_dvec);
        cudaGetSymbolAddress((void**)&P.attu, g_attu);
        cudaGetSymbolAddress((void**)&P.xl,   g_xl);
        cudaGetSymbolAddress((void**)&P.hatt, g_hatt);
        cudaGetSymbolAddress((void**)&P.catt, g_catt);
        cudaGetSymbolAddress((void**)&P.hlang,g_hlang);
        cudaGetSymbolAddress((void**)&P.clang,g_clang);
        cudaGetSymbolAddress((void**)&P.Vra, g_Vra); cudaGetSymbolAddress((void**)&P.Vca, g_Vca);
        cudaGetSymbolAddress((void**)&P.Vrb, g_Vrb); cudaGetSymbolAddress((void**)&P.Vcb, g_Vcb);
        cudaGetSymbolAddress((void**)&P.smm, g_smm); cudaGetSymbolAddress((void**)&P.sm1, g_sm1);
        cudaGetSymbolAddress((void**)&P.s1m, g_s1m); cudaGetSymbolAddress((void**)&P.s11, g_s11);
        cudaGetSymbolAddress((void**)&P.ra, g_ra); cudaGetSymbolAddress((void**)&P.rb, g_rb);
        cudaGetSymbolAddress((void**)&P.ca, g_ca); cudaGetSymbolAddress((void**)&P.cb, g_cb);
        cudaGetSymbolAddress((void**)&P.Ph, g_Ph);
        cudaGetSymbolAddress((void**)&P.Qh, g_Qh); cudaGetSymbolAddress((void**)&P.Ql, g_Ql);
        cudaGetSymbolAddress((void**)&P.Sh, g_Sh); cudaGetSymbolAddress((void**)&P.Sl, g_Sl);
        cudaGetSymbolAddress((void**)&P.Z0h, g_Z0h);
        cudaGetSymbolAddress((void**)&P.ADJh, g_ADJh);
        cudaGetSymbolAddress((void**)&P.W1h, g_W1h); cudaGetSymbolAddress((void**)&P.W1l, g_W1l);
        cudaGetSymbolAddress((void**)&P.W2h, g_W2h); cudaGetSymbolAddress((void**)&P.W2l, g_W2l);
        cudaGetSymbolAddress((void**)&P.Wmh, g_Wmh); cudaGetSymbolAddress((void**)&P.Wml, g_Wml);
        cudaGetSymbolAddress((void**)&P.G0h, g_G0h);
        cudaGetSymbolAddress((void**)&P.G1h, g_G1h);
        cudaGetSymbolAddress((void**)&P.G2h, g_G2h);
        cudaFuncSetAttribute(hmma_gemm<1>, cudaFuncAttributeMaxDynamicSharedMemorySize, MMA_SMEM);
        cudaFuncSetAttribute(hmma_gemm<2>, cudaFuncAttributeMaxDynamicSharedMemorySize, MMA_SMEM);
        cudaFuncSetAttribute(hmma_gemm<3>, cudaFuncAttributeMaxDynamicSharedMemorySize, MMA_SMEM);
        cudaFuncSetAttribute(hmma_gemm<4>, cudaFuncAttributeMaxDynamicSharedMemorySize, MMA_SMEM);
        cudaStreamCreateWithFlags(&g_s2, cudaStreamNonBlocking);
        cudaEventCreateWithFlags(&g_ev1, cudaEventDisableTiming);
        cudaEventCreateWithFlags(&g_ev_mv, cudaEventDisableTiming);
        cudaEventCreateWithFlags(&g_ev_adj, cudaEventDisableTiming);
        cudaEventCreateWithFlags(&g_ev3, cudaEventDisableTiming);
        g_init = true;
    }

    const float* prev_h = sh + BR;
    const float* h0 = sh;
    const float* c0 = sc;
    const float* c1 = sc + BR;

    // ---- fork ----
    cudaEventRecord(g_ev1, 0);
    cudaStreamWaitEvent(g_s2, g_ev1, 0);

    // s2: GEM conversion -> Wmt -> U -> Adj_core (all independent of LSTM chain)
    conv_mask_kernel<<<(int)((NGE/4+255)/256),256,0,g_s2>>>(ge, mask, P.Ph, NGE/4, P.minu);
    tconv2_kernel<<<dim3(32,32),dim3(32,8),0,g_s2>>>(e1W, 2048, P.W1h, P.W1l);
    tconv2_kernel<<<dim3(32,32),dim3(32,8),0,g_s2>>>(e2W, 2048, P.W2h, P.W2l);
    hmma_gemm<3><<<dim3(8,8,1),128,MMA_SMEM,g_s2>>>(P.W2h,P.W2l,1024,0, P.W1h,P.W1l,1024,0,
        1024, 0, 1, 0, nullptr,0, P.Wmh,P.Wml,1024, nullptr,nullptr,nullptr,nullptr,nullptr);
    mv_kernel<<<4,256,0,g_s2>>>(e2b, e1W, 2048, P.Vrb);
    mv_kernel<<<4,256,0,g_s2>>>(e1b, e2W, 2048, P.Vcb);
    cudaEventRecord(g_ev_mv, g_s2);
    hmma_gemm<2><<<dim3(8,256,1),128,MMA_SMEM,g_s2>>>(P.Ph,nullptr,1024,0, P.Wmh,P.Wml,1024,0,
        1024, 0, 1, 0, nullptr,0, P.Qh,P.Ql,1024, nullptr,nullptr,nullptr,nullptr,nullptr);
    hmma_gemm<4><<<dim3(4,4,64),128,MMA_SMEM,g_s2>>>(P.Qh,P.Ql,1024,(long)NN*RR, P.Ph,nullptr,1024,(long)NN*RR,
        1024, 512, 0, 0, P.adj,512, nullptr,nullptr,0, nullptr,nullptr,nullptr,nullptr,nullptr);
    cudaEventRecord(g_ev_adj, g_s2);
    tconv_kernel<<<dim3(32,32),dim3(32,8),0,g_s2>>>(gW1, 1024, 1024, P.G1h);
    tconv_kernel<<<dim3(32,32),dim3(32,8),0,g_s2>>>(gW2, 1024, 1024, P.G2h);
    clear_attu<<<BB*RR/256,256,0,g_s2>>>(P.attu);
    cudaEventRecord(g_ev3, g_s2);

    // default: LSTM chain + rank-1 prep + Z0
    concat3_kernel<<<(BB*3072+255)/256,256>>>(prev_h, fc, xt, P.xcat);
    sgemm(true, P.xcat,3072, aWih,3072, P.part,            4096, BB,4096,3072, 3);
    sgemm(true, h0,1024,     aWhh,1024, P.part+3*BB*4096,  4096, BB,4096,1024, 1);
    reduce_kernel<<<(BB*4096+255)/256,256>>>(P.gates, P.part, BB*4096, 4, 4095, abih, abhh);
    lstm_kernel<<<(BR+255)/256,256>>>(P.gates, c0, P.hatt, P.catt);
    sgemm(true, P.hatt,1024, e1W+1024,2048, P.part, 1024, BB,1024,1024, 4);
    reduce_kernel<<<(BB*1024+255)/256,256>>>(P.ht1, P.part, BB*1024, 4, 1023, nullptr, nullptr);
    sgemm(true, P.hatt,1024, e2W+1024,2048, P.part, 1024, BB,1024,1024, 4);
    reduce_kernel<<<(BB*1024+255)/256,256>>>(P.ht2, P.part, BB*1024, 4, 1023, nullptr, nullptr);
    sgemm(false, prev_h,1024, gW0+1024*1024,1024, P.part, 1024, BB,1024,1024, 4);
    reduce_kernel<<<(BB*1024+255)/256,256>>>(P.pvec, P.part, BB*1024, 4, 1023, nullptr, nullptr);
    sgemm(false, P.ht2,1024, e1W,2048, P.Vra, 1024, BB,1024,1024, 1);
    sgemm(false, P.ht1,1024, e2W,2048, P.Vca, 1024, BB,1024,1024, 1);
    scalars_kernel<<<BB,256>>>(P.ht1, P.ht2, e1b, e2b, P.smm, P.sm1, P.s1m, P.s11);
    cudaStreamWaitEvent(0, g_ev_mv, 0);   // GEM + Vrb/Vcb ready
    ranks_kernel<<<BB*NN/8,256>>>(P.Ph, P.Vra, P.Vrb, P.Vca, P.Vcb,
                                  P.smm, P.sm1, P.s1m, P.s11, mask,
                                  P.ra, P.rb, P.ca, P.cb);
    // Z0 = GEM@G0 (default stream; GEM already ready via ev_mv wait)
    tconv_kernel<<<dim3(32,32),dim3(32,8)>>>(gW0, 1024, 1024, P.G0h);
    hmma_gemm<1><<<dim3(8,256,1),128,MMA_SMEM>>>(P.Ph,nullptr,1024,0, P.G0h,nullptr,1024,0,
        1024, 0, 2, 0, nullptr,0, P.Z0h,nullptr,0, nullptr,nullptr,nullptr,nullptr,nullptr);

    cudaStreamWaitEvent(0, g_ev_adj, 0);  // Adj_core ready

    // ---- Adj epilogue (rank-1 + batch-min), topk, rowfinal ----
    adj_epi_kernel<<<BB*NN/8,256>>>(P.adj, P.ra, P.rb, P.ca, P.cb, mask, P.minu);
    topk_kernel<<<BB*NN,512>>>(P.adj, P.minu, mask, P.ADJh, P.dvec);
    rowfinal_kernel<<<BB*NN/8,256>>>(P.ADJh, P.dvec, mask, P.srow);

    cudaStreamWaitEvent(0, g_ev3, 0);     // G1/G2, attu clear ready

    // ---- GCN layer 0 ----
    hmma_gemm<1><<<dim3(8,4,64),128,MMA_SMEM>>>(P.ADJh,nullptr,512,(long)NN*NN, P.Z0h,nullptr,512,(long)RR*NN,
        512, 512, 1, 1, nullptr,0, P.Sh,nullptr,1024, gb0, P.pvec, P.srow, mask, nullptr);

    // ---- GCN layer 1 ----
    hmma_gemm<1><<<dim3(8,256,1),128,MMA_SMEM>>>(P.Sh,nullptr,1024,0, P.G1h,nullptr,1024,0,
        1024, 0, 2, 0, nullptr,0, P.Ph,nullptr,0, nullptr,nullptr,nullptr,nullptr,nullptr);
    hmma_gemm<1><<<dim3(8,4,64),128,MMA_SMEM>>>(P.ADJh,nullptr,512,(long)NN*NN, P.Ph,nullptr,512,(long)RR*NN,
        512, 512, 1, 1, nullptr,0, P.Qh,nullptr,1024, gb1, nullptr, nullptr, mask, nullptr);

    // ---- GCN layer 2 (fused col-max) ----
    hmma_gemm<1><<<dim3(8,256,1),128,MMA_SMEM>>>(P.Qh,nullptr,1024,0, P.G2h,nullptr,1024,0,
        1024, 0, 2, 0, nullptr,0, P.Sh,nullptr,0, nullptr,nullptr,nullptr,nullptr,nullptr);
    hmma_gemm<1><<<dim3(8,4,64),128,MMA_SMEM>>>(P.ADJh,nullptr,512,(long)NN*NN, P.Sh,nullptr,512,(long)RR*NN,
        512, 512, 3, 1, nullptr,0, nullptr,nullptr,0, gb2, nullptr, nullptr, mask, P.attu);

    // ---- language LSTM ----
    concat2_kernel<<<(BB*2048+255)/256,256>>>(P.attu, P.hatt, P.xl);
    sgemm(true, P.xl,2048,   lWih,2048, P.part,           4096, BB,4096,2048, 2);
    sgemm(true, prev_h,1024, lWhh,1024, P.part+2*BB*4096, 4096, BB,4096,1024, 1);
    reduce_kernel<<<(BB*4096+255)/256,256>>>(P.gates2, P.part, BB*4096, 3, 4095, lbih, lbhh);
    lstm_kernel<<<(BR+255)/256,256>>>(P.gates2, c1, P.hlang, P.clang);

    pack_kernel<<<(BR+255)/256,256>>>(P.hatt, P.catt, P.hlang, P.clang, out, out_size);
}